// round 1
// baseline (speedup 1.0000x reference)
#include <cuda_runtime.h>
#include <cstdint>

// ---------------------------------------------------------------------------
// Chebyshev KAN: two layers, each layer = column min/max normalize ->
// Chebyshev expansion (deg 8) -> GEMM with K = features * 9.
// Layer1: [16384,1024] -> [16384,2048]; Layer2: -> [16384,1024]. fp32.
// ---------------------------------------------------------------------------

#define BATCH   16384
#define IN_DIM  1024
#define HID_DIM 2048
#define OUT_DIM 1024
#define NT      9          // degree 8 -> 9 Chebyshev terms

// ------------------------------ scratch ------------------------------------
__device__ float    g_h  [(size_t)BATCH * HID_DIM];          // 128 MB
__device__ float    g_ct1[(size_t)IN_DIM  * NT * HID_DIM];   // 75.5 MB
__device__ float    g_ct2[(size_t)HID_DIM * NT * OUT_DIM];   // 75.5 MB
__device__ unsigned g_mink[HID_DIM];
__device__ unsigned g_maxk[HID_DIM];
__device__ float    g_mn[HID_DIM];
__device__ float    g_sc[HID_DIM];

// ---------------------- ordered-uint float keys ----------------------------
__device__ __forceinline__ unsigned fkey(float f) {
    unsigned u = __float_as_uint(f);
    return (u & 0x80000000u) ? ~u : (u | 0x80000000u);
}
__device__ __forceinline__ float funkey(unsigned u) {
    return __uint_as_float((u & 0x80000000u) ? (u ^ 0x80000000u) : ~u);
}

// --------------------------- aux kernels -----------------------------------
__global__ void minmax_init(unsigned* mink, unsigned* maxk, int F) {
    int c = blockIdx.x * blockDim.x + threadIdx.x;
    if (c < F) { mink[c] = 0xFFFFFFFFu; maxk[c] = 0u; }
}

// Each thread owns one column within a 256-row chunk; one atomic per chunk.
__global__ void colminmax(const float* __restrict__ X, int F, int chunk,
                          unsigned* mink, unsigned* maxk) {
    int c  = blockIdx.x * blockDim.x + threadIdx.x;
    int r0 = blockIdx.y * chunk;
    float lo =  3.402823466e38f;
    float hi = -3.402823466e38f;
    const float* p = X + (size_t)r0 * F + c;
    for (int r = 0; r < chunk; ++r) {
        float v = p[(size_t)r * F];
        lo = fminf(lo, v);
        hi = fmaxf(hi, v);
    }
    atomicMin(&mink[c], fkey(lo));
    atomicMax(&maxk[c], fkey(hi));
}

__global__ void finalize_minmax(const unsigned* mink, const unsigned* maxk,
                                float* mn, float* sc, int F) {
    int c = blockIdx.x * blockDim.x + threadIdx.x;
    if (c < F) {
        float lo = funkey(mink[c]);
        float hi = funkey(maxk[c]);
        mn[c] = lo;
        sc[c] = 2.0f / (hi - lo);
    }
}

// coeffs [I, O, 9] -> ct [(i*9+d), O]   (both sides coalesced via smem tile)
__global__ void transpose_coeffs(const float* __restrict__ c,
                                 float* __restrict__ ct, int O) {
    __shared__ float s[128 * NT];
    int i  = blockIdx.y;
    int o0 = blockIdx.x * 128;
    const float* src = c + ((size_t)i * O + o0) * NT;
    for (int j = threadIdx.x; j < 128 * NT; j += 128) s[j] = src[j];
    __syncthreads();
    int o = o0 + threadIdx.x;
    #pragma unroll
    for (int d = 0; d < NT; ++d)
        ct[((size_t)i * NT + d) * O + o] = s[threadIdx.x * NT + d];
}

// ------------------------------ fused GEMM ---------------------------------
// out[b,o] = sum_{i,d} T_d(xn[b,i]) * Bt[(i*9+d), o]
// Tile: BM=128, BN=128, BK=36 (4 features x 9 terms), 256 thr, 8x8 microtile.
__global__ void __launch_bounds__(256) kan_gemm(
    const float* __restrict__ X,    // [BATCH, F]
    const float* __restrict__ Bt,   // [F*9, O]
    const float* __restrict__ mn,
    const float* __restrict__ sc,
    float* __restrict__ out,        // [BATCH, O]
    int F, int O)
{
    const int BM = 128, BN = 128, KF = 4, BK = KF * NT;  // 36
    __shared__ float As[BK][BM];
    __shared__ float Bs[BK][BN];

    const int tid   = threadIdx.x;
    const int brow0 = blockIdx.y * BM;
    const int oc0   = blockIdx.x * BN;
    const int tm    = (tid >> 4) << 3;   // (tid/16)*8
    const int tn    = (tid & 15) << 3;   // (tid%16)*8

    float acc[8][8];
    #pragma unroll
    for (int m = 0; m < 8; ++m)
        #pragma unroll
        for (int n = 0; n < 8; ++n) acc[m][n] = 0.0f;

    for (int f0 = 0; f0 < F; f0 += KF) {
        // --- A tile: 128 rows x 4 features, Chebyshev-expanded to 36 k-rows
        if (tid < 128) {
            const int r = tid;
            const float4 xv = *reinterpret_cast<const float4*>(
                &X[(size_t)(brow0 + r) * F + f0]);
            float xs[4] = {xv.x, xv.y, xv.z, xv.w};
            #pragma unroll
            for (int fl = 0; fl < 4; ++fl) {
                int f    = f0 + fl;
                float xn = (xs[fl] - mn[f]) * sc[f] - 1.0f;
                float x2 = xn + xn;
                As[fl * NT + 0][r] = 1.0f;
                As[fl * NT + 1][r] = xn;
                float tp = 1.0f, tc = xn;
                #pragma unroll
                for (int d = 2; d < NT; ++d) {
                    float t = fmaf(x2, tc, -tp);
                    As[fl * NT + d][r] = t;
                    tp = tc; tc = t;
                }
            }
        }
        // --- B tile: 36 x 128, coalesced
        {
            const float* bsrc = Bt + (size_t)f0 * NT * O + oc0;
            #pragma unroll
            for (int j = 0; j < 18; ++j) {
                int e = tid + j * 256;   // 0..4607
                int k = e >> 7;
                int o = e & 127;
                Bs[k][o] = bsrc[(size_t)k * O + o];
            }
        }
        __syncthreads();

        #pragma unroll 9
        for (int kk = 0; kk < BK; ++kk) {
            float a[8], b[8];
            *reinterpret_cast<float4*>(a)     = *reinterpret_cast<const float4*>(&As[kk][tm]);
            *reinterpret_cast<float4*>(a + 4) = *reinterpret_cast<const float4*>(&As[kk][tm + 4]);
            *reinterpret_cast<float4*>(b)     = *reinterpret_cast<const float4*>(&Bs[kk][tn]);
            *reinterpret_cast<float4*>(b + 4) = *reinterpret_cast<const float4*>(&Bs[kk][tn + 4]);
            #pragma unroll
            for (int m = 0; m < 8; ++m)
                #pragma unroll
                for (int n = 0; n < 8; ++n)
                    acc[m][n] = fmaf(a[m], b[n], acc[m][n]);
        }
        __syncthreads();
    }

    #pragma unroll
    for (int m = 0; m < 8; ++m) {
        float* orow = &out[(size_t)(brow0 + tm + m) * O + oc0 + tn];
        float4 v0 = {acc[m][0], acc[m][1], acc[m][2], acc[m][3]};
        float4 v1 = {acc[m][4], acc[m][5], acc[m][6], acc[m][7]};
        *reinterpret_cast<float4*>(orow)     = v0;
        *reinterpret_cast<float4*>(orow + 4) = v1;
    }
}

// ------------------------------ launcher -----------------------------------
extern "C" void kernel_launch(void* const* d_in, const int* in_sizes, int n_in,
                              void* d_out, int out_size) {
    const float* x  = (const float*)d_in[0];   // [16384, 1024]
    const float* c1 = (const float*)d_in[1];   // [1024, 2048, 9]
    const float* c2 = (const float*)d_in[2];   // [2048, 1024, 9]
    float* y = (float*)d_out;                  // [16384, 1024]

    float *h, *ct1, *ct2, *mn, *sc;
    unsigned *mink, *maxk;
    cudaGetSymbolAddress((void**)&h,    g_h);
    cudaGetSymbolAddress((void**)&ct1,  g_ct1);
    cudaGetSymbolAddress((void**)&ct2,  g_ct2);
    cudaGetSymbolAddress((void**)&mink, g_mink);
    cudaGetSymbolAddress((void**)&maxk, g_maxk);
    cudaGetSymbolAddress((void**)&mn,   g_mn);
    cudaGetSymbolAddress((void**)&sc,   g_sc);

    const int CHUNK = 256;                     // 16384 / 64 chunks

    // Pre-transpose coefficient tensors to [k, o] layout.
    transpose_coeffs<<<dim3(HID_DIM / 128, IN_DIM),  128>>>(c1, ct1, HID_DIM);
    transpose_coeffs<<<dim3(OUT_DIM / 128, HID_DIM), 128>>>(c2, ct2, OUT_DIM);

    // ---- layer 1 ----
    minmax_init<<<IN_DIM / 256, 256>>>(mink, maxk, IN_DIM);
    colminmax<<<dim3(IN_DIM / 256, BATCH / CHUNK), 256>>>(x, IN_DIM, CHUNK, mink, maxk);
    finalize_minmax<<<IN_DIM / 256, 256>>>(mink, maxk, mn, sc, IN_DIM);
    kan_gemm<<<dim3(HID_DIM / 128, BATCH / 128), 256>>>(x, ct1, mn, sc, h, IN_DIM, HID_DIM);

    // ---- layer 2 ----
    minmax_init<<<HID_DIM / 256, 256>>>(mink, maxk, HID_DIM);
    colminmax<<<dim3(HID_DIM / 256, BATCH / CHUNK), 256>>>(h, HID_DIM, CHUNK, mink, maxk);
    finalize_minmax<<<HID_DIM / 256, 256>>>(mink, maxk, mn, sc, HID_DIM);
    kan_gemm<<<dim3(OUT_DIM / 128, BATCH / 128), 256>>>(h, ct2, mn, sc, y, HID_DIM, OUT_DIM);
}

// round 3
// speedup vs baseline: 1.0018x; 1.0018x over previous
#include <cuda_runtime.h>
#include <cstdint>

// ---------------------------------------------------------------------------
// Chebyshev KAN: two layers, each layer = column min/max normalize ->
// Chebyshev expansion (deg 8) -> GEMM with K = features * 9.
// Layer1: [16384,1024] -> [16384,2048]; Layer2: -> [16384,1024]. fp32.
// ---------------------------------------------------------------------------

#define BATCH   16384
#define IN_DIM  1024
#define HID_DIM 2048
#define OUT_DIM 1024
#define NT      9          // degree 8 -> 9 Chebyshev terms

// ------------------------------ scratch ------------------------------------
__device__ float    g_h  [(size_t)BATCH * HID_DIM];          // 128 MB
__device__ float    g_ct1[(size_t)IN_DIM  * NT * HID_DIM];   // 75.5 MB
__device__ float    g_ct2[(size_t)HID_DIM * NT * OUT_DIM];   // 75.5 MB
__device__ unsigned g_mink[HID_DIM];
__device__ unsigned g_maxk[HID_DIM];
__device__ float    g_mn[HID_DIM];
__device__ float    g_sc[HID_DIM];

// ---------------------- ordered-uint float keys ----------------------------
__device__ __forceinline__ unsigned fkey(float f) {
    unsigned u = __float_as_uint(f);
    return (u & 0x80000000u) ? ~u : (u | 0x80000000u);
}
__device__ __forceinline__ float funkey(unsigned u) {
    return __uint_as_float((u & 0x80000000u) ? (u ^ 0x80000000u) : ~u);
}

// --------------------------- aux kernels -----------------------------------
__global__ void minmax_init(unsigned* mink, unsigned* maxk, int F) {
    int c = blockIdx.x * blockDim.x + threadIdx.x;
    if (c < F) { mink[c] = 0xFFFFFFFFu; maxk[c] = 0u; }
}

// Each thread owns one column within a 256-row chunk; one atomic per chunk.
__global__ void colminmax(const float* __restrict__ X, int F, int chunk,
                          unsigned* mink, unsigned* maxk) {
    int c  = blockIdx.x * blockDim.x + threadIdx.x;
    int r0 = blockIdx.y * chunk;
    float lo =  3.402823466e38f;
    float hi = -3.402823466e38f;
    const float* p = X + (size_t)r0 * F + c;
    for (int r = 0; r < chunk; ++r) {
        float v = p[(size_t)r * F];
        lo = fminf(lo, v);
        hi = fmaxf(hi, v);
    }
    atomicMin(&mink[c], fkey(lo));
    atomicMax(&maxk[c], fkey(hi));
}

__global__ void finalize_minmax(const unsigned* mink, const unsigned* maxk,
                                float* mn, float* sc, int F) {
    int c = blockIdx.x * blockDim.x + threadIdx.x;
    if (c < F) {
        float lo = funkey(mink[c]);
        float hi = funkey(maxk[c]);
        mn[c] = lo;
        sc[c] = 2.0f / (hi - lo);
    }
}

// coeffs [I, O, 9] -> ct [(i*9+d), O]   (both sides coalesced via smem tile)
__global__ void transpose_coeffs(const float* __restrict__ c,
                                 float* __restrict__ ct, int O) {
    __shared__ float s[128 * NT];
    int i  = blockIdx.y;
    int o0 = blockIdx.x * 128;
    const float* src = c + ((size_t)i * O + o0) * NT;
    for (int j = threadIdx.x; j < 128 * NT; j += 128) s[j] = src[j];
    __syncthreads();
    int o = o0 + threadIdx.x;
    #pragma unroll
    for (int d = 0; d < NT; ++d)
        ct[((size_t)i * NT + d) * O + o] = s[threadIdx.x * NT + d];
}

// ------------------------------ fused GEMM ---------------------------------
// out[b,o] = sum_{i,d} T_d(xn[b,i]) * Bt[(i*9+d), o]
// Tile: BM=128, BN=128, BK=36 (4 features x 9 terms), 256 thr, 8x8 microtile.
__global__ void __launch_bounds__(256) kan_gemm(
    const float* __restrict__ X,    // [BATCH, F]
    const float* __restrict__ Bt,   // [F*9, O]
    const float* __restrict__ mn,
    const float* __restrict__ sc,
    float* __restrict__ out,        // [BATCH, O]
    int F, int O)
{
    const int BM = 128, BN = 128, KF = 4, BK = KF * NT;  // 36
    __shared__ float As[BK][BM];
    __shared__ float Bs[BK][BN];

    const int tid   = threadIdx.x;
    const int brow0 = blockIdx.y * BM;
    const int oc0   = blockIdx.x * BN;
    const int tm    = (tid >> 4) << 3;   // (tid/16)*8
    const int tn    = (tid & 15) << 3;   // (tid%16)*8

    float acc[8][8];
    #pragma unroll
    for (int m = 0; m < 8; ++m)
        #pragma unroll
        for (int n = 0; n < 8; ++n) acc[m][n] = 0.0f;

    for (int f0 = 0; f0 < F; f0 += KF) {
        // --- A tile: 128 rows x 4 features, Chebyshev-expanded to 36 k-rows
        if (tid < 128) {
            const int r = tid;
            const float4 xv = *reinterpret_cast<const float4*>(
                &X[(size_t)(brow0 + r) * F + f0]);
            float xs[4] = {xv.x, xv.y, xv.z, xv.w};
            #pragma unroll
            for (int fl = 0; fl < 4; ++fl) {
                int f    = f0 + fl;
                float xn = (xs[fl] - mn[f]) * sc[f] - 1.0f;
                float x2 = xn + xn;
                As[fl * NT + 0][r] = 1.0f;
                As[fl * NT + 1][r] = xn;
                float tp = 1.0f, tc = xn;
                #pragma unroll
                for (int d = 2; d < NT; ++d) {
                    float t = fmaf(x2, tc, -tp);
                    As[fl * NT + d][r] = t;
                    tp = tc; tc = t;
                }
            }
        }
        // --- B tile: 36 x 128, coalesced
        {
            const float* bsrc = Bt + (size_t)f0 * NT * O + oc0;
            #pragma unroll
            for (int j = 0; j < 18; ++j) {
                int e = tid + j * 256;   // 0..4607
                int k = e >> 7;
                int o = e & 127;
                Bs[k][o] = bsrc[(size_t)k * O + o];
            }
        }
        __syncthreads();

        #pragma unroll 9
        for (int kk = 0; kk < BK; ++kk) {
            float a[8], b[8];
            *reinterpret_cast<float4*>(a)     = *reinterpret_cast<const float4*>(&As[kk][tm]);
            *reinterpret_cast<float4*>(a + 4) = *reinterpret_cast<const float4*>(&As[kk][tm + 4]);
            *reinterpret_cast<float4*>(b)     = *reinterpret_cast<const float4*>(&Bs[kk][tn]);
            *reinterpret_cast<float4*>(b + 4) = *reinterpret_cast<const float4*>(&Bs[kk][tn + 4]);
            #pragma unroll
            for (int m = 0; m < 8; ++m)
                #pragma unroll
                for (int n = 0; n < 8; ++n)
                    acc[m][n] = fmaf(a[m], b[n], acc[m][n]);
        }
        __syncthreads();
    }

    #pragma unroll
    for (int m = 0; m < 8; ++m) {
        float* orow = &out[(size_t)(brow0 + tm + m) * O + oc0 + tn];
        float4 v0 = {acc[m][0], acc[m][1], acc[m][2], acc[m][3]};
        float4 v1 = {acc[m][4], acc[m][5], acc[m][6], acc[m][7]};
        *reinterpret_cast<float4*>(orow)     = v0;
        *reinterpret_cast<float4*>(orow + 4) = v1;
    }
}

// ------------------------------ launcher -----------------------------------
extern "C" void kernel_launch(void* const* d_in, const int* in_sizes, int n_in,
                              void* d_out, int out_size) {
    const float* x  = (const float*)d_in[0];   // [16384, 1024]
    const float* c1 = (const float*)d_in[1];   // [1024, 2048, 9]
    const float* c2 = (const float*)d_in[2];   // [2048, 1024, 9]
    float* y = (float*)d_out;                  // [16384, 1024]

    float *h, *ct1, *ct2, *mn, *sc;
    unsigned *mink, *maxk;
    cudaGetSymbolAddress((void**)&h,    g_h);
    cudaGetSymbolAddress((void**)&ct1,  g_ct1);
    cudaGetSymbolAddress((void**)&ct2,  g_ct2);
    cudaGetSymbolAddress((void**)&mink, g_mink);
    cudaGetSymbolAddress((void**)&maxk, g_maxk);
    cudaGetSymbolAddress((void**)&mn,   g_mn);
    cudaGetSymbolAddress((void**)&sc,   g_sc);

    const int CHUNK = 256;                     // 16384 / 64 chunks

    // Pre-transpose coefficient tensors to [k, o] layout.
    transpose_coeffs<<<dim3(HID_DIM / 128, IN_DIM),  128>>>(c1, ct1, HID_DIM);
    transpose_coeffs<<<dim3(OUT_DIM / 128, HID_DIM), 128>>>(c2, ct2, OUT_DIM);

    // ---- layer 1 ----
    minmax_init<<<IN_DIM / 256, 256>>>(mink, maxk, IN_DIM);
    colminmax<<<dim3(IN_DIM / 256, BATCH / CHUNK), 256>>>(x, IN_DIM, CHUNK, mink, maxk);
    finalize_minmax<<<IN_DIM / 256, 256>>>(mink, maxk, mn, sc, IN_DIM);
    kan_gemm<<<dim3(HID_DIM / 128, BATCH / 128), 256>>>(x, ct1, mn, sc, h, IN_DIM, HID_DIM);

    // ---- layer 2 ----
    minmax_init<<<HID_DIM / 256, 256>>>(mink, maxk, HID_DIM);
    colminmax<<<dim3(HID_DIM / 256, BATCH / CHUNK), 256>>>(h, HID_DIM, CHUNK, mink, maxk);
    finalize_minmax<<<HID_DIM / 256, 256>>>(mink, maxk, mn, sc, HID_DIM);
    kan_gemm<<<dim3(OUT_DIM / 128, BATCH / 128), 256>>>(h, ct2, mn, sc, y, HID_DIM, OUT_DIM);
}

// round 5
// speedup vs baseline: 2.2395x; 2.2355x over previous
#include <cuda_runtime.h>
#include <cuda_bf16.h>
#include <cstdint>

#define BATCH   16384
#define IN_DIM  1024
#define HID_DIM 2048
#define OUT_DIM 1024

#define SA        296                 // padded k-stride (bf16 elems); 592B rows, conflict-free ldmatrix
#define TILE_B    (128 * SA * 2)      // 75776 bytes per operand tile
#define TILE_U32  (TILE_B / 4)        // 18944

// ------------------------------ scratch ------------------------------------
__device__ float    g_h [(size_t)BATCH * HID_DIM];
__device__ unsigned g_b1[(size_t)16 * 64  * TILE_U32];   // layer1 packed B images
__device__ unsigned g_b2[(size_t)8  * 128 * TILE_U32];   // layer2 packed B images
__device__ unsigned g_mink[HID_DIM], g_maxk[HID_DIM];
__device__ float    g_mn[HID_DIM],   g_sc[HID_DIM];

// ---------------------------- helpers --------------------------------------
__device__ __forceinline__ unsigned fkey(float f) {
    unsigned u = __float_as_uint(f);
    return (u & 0x80000000u) ? ~u : (u | 0x80000000u);
}
__device__ __forceinline__ float funkey(unsigned u) {
    return __uint_as_float((u & 0x80000000u) ? (u ^ 0x80000000u) : ~u);
}
__device__ __forceinline__ void cp16(unsigned s, const void* g) {
    asm volatile("cp.async.cg.shared.global [%0], [%1], 16;" :: "r"(s), "l"(g) : "memory");
}
__device__ __forceinline__ void ldsm4(unsigned addr, unsigned* r) {
    asm volatile("ldmatrix.sync.aligned.m8n8.x4.shared.b16 {%0,%1,%2,%3}, [%4];"
                 : "=r"(r[0]), "=r"(r[1]), "=r"(r[2]), "=r"(r[3]) : "r"(addr));
}
__device__ __forceinline__ void mma16816(float* c, const unsigned* a,
                                         unsigned b0, unsigned b1) {
    asm volatile(
        "mma.sync.aligned.m16n8k16.row.col.f32.bf16.bf16.f32 "
        "{%0,%1,%2,%3}, {%4,%5,%6,%7}, {%8,%9}, {%0,%1,%2,%3};"
        : "+f"(c[0]), "+f"(c[1]), "+f"(c[2]), "+f"(c[3])
        : "r"(a[0]), "r"(a[1]), "r"(a[2]), "r"(a[3]), "r"(b0), "r"(b1));
}

// --------------------------- min/max kernels -------------------------------
__global__ void minmax_init(unsigned* mink, unsigned* maxk, int F) {
    int c = blockIdx.x * blockDim.x + threadIdx.x;
    if (c < F) { mink[c] = 0xFFFFFFFFu; maxk[c] = 0u; }
}
__global__ void colminmax(const float* __restrict__ X, int F, int chunk,
                          unsigned* mink, unsigned* maxk) {
    int c  = blockIdx.x * blockDim.x + threadIdx.x;
    int r0 = blockIdx.y * chunk;
    float lo =  3.402823466e38f, hi = -3.402823466e38f;
    const float* p = X + (size_t)r0 * F + c;
    for (int r = 0; r < chunk; ++r) {
        float v = p[(size_t)r * F];
        lo = fminf(lo, v); hi = fmaxf(hi, v);
    }
    atomicMin(&mink[c], fkey(lo));
    atomicMax(&maxk[c], fkey(hi));
}
__global__ void finalize_minmax(const unsigned* mink, const unsigned* maxk,
                                float* mn, float* sc, int F) {
    int c = blockIdx.x * blockDim.x + threadIdx.x;
    if (c < F) {
        float lo = funkey(mink[c]), hi = funkey(maxk[c]);
        mn[c] = lo; sc[c] = 2.0f / (hi - lo);
    }
}

// ------------------------------ B prep -------------------------------------
// coeffs [F,O,9] fp32 -> per (nblock, chunk): exact 75776B smem image.
// row n (0..127), k<144: hi = bf16(c[d*16+il]); 144<=k<288: lo residual;
// k 288..295: zero pad. n-major, stride SA bf16.
__global__ void prep_B(const float* __restrict__ coeffs,
                       unsigned* __restrict__ outB, int F, int O) {
    extern __shared__ float stag[];            // [il][n][d] = 16*128*9 floats
    const int nb = blockIdx.x, c = blockIdx.y, tid = threadIdx.x;
    const float* src = coeffs + ((size_t)(c * 16) * O + (size_t)nb * 128) * 9;
    for (int idx = tid; idx < 18432; idx += 256) {
        int il = idx / 1152, rem = idx - il * 1152;      // rem = n*9 + d
        stag[idx] = src[(size_t)il * O * 9 + rem];
    }
    __syncthreads();
    const int nch = F / 16;
    unsigned* dst = outB + ((size_t)nb * nch + c) * TILE_U32;
    for (int j = tid; j < TILE_U32; j += 256) {
        int nn = j / (SA / 2);
        int k0 = (j - nn * (SA / 2)) * 2;
        unsigned outv = 0;
        if (k0 < 288) {
            #pragma unroll
            for (int e = 0; e < 2; ++e) {
                int k = k0 + e;
                int half = (k >= 144) ? 1 : 0;
                int kk = k - 144 * half;
                int d = kk >> 4, il = kk & 15;
                float v = stag[il * 1152 + nn * 9 + d];
                __nv_bfloat16 hi = __float2bfloat16(v);
                unsigned short us;
                if (half)
                    us = __bfloat16_as_ushort(__float2bfloat16(v - __bfloat162float(hi)));
                else
                    us = __bfloat16_as_ushort(hi);
                outv |= (unsigned)us << (16 * e);
            }
        }
        dst[j] = outv;
    }
}

// ------------------------- fused mma.sync GEMM -----------------------------
// C[128,128] per CTA = sum over chunks of [Ah|Al](gen) x [Bh|Bl](prepped),
// 3-term split: Ah*Bh + Ah*Bl + Al*Bh. 8 warps, warp tile 64x32.
__global__ void __launch_bounds__(256, 1)
kan_mma(const float* __restrict__ X, const unsigned* __restrict__ gB,
        const float* __restrict__ mn, const float* __restrict__ sc,
        float* __restrict__ out, int F, int O)
{
    extern __shared__ __align__(16) char smem[];
    __nv_bfloat16* As = (__nv_bfloat16*)smem;                 // 128 x SA
    const unsigned A_u  = (unsigned)__cvta_generic_to_shared(smem);
    const unsigned B0_u = A_u + TILE_B;                        // double buffer

    const int tid  = threadIdx.x;
    const int wid  = tid >> 5;
    const int lane = tid & 31;
    const int brow0 = blockIdx.y * 128;
    const int oc0   = blockIdx.x * 128;
    const int nch   = F / 16;
    const unsigned* gb = gB + (size_t)blockIdx.x * nch * TILE_U32;

    // ldmatrix per-lane byte offsets (k added per slab)
    const int wm = (wid >> 2) * 64;
    const int wn = (wid & 3) * 32;
    const int lrow = ((lane >> 3) & 1) * 8 + (lane & 7);
    const int lcol = (lane >> 4) * 8;
    unsigned offA[4], offB[2];
    #pragma unroll
    for (int i = 0; i < 4; ++i) offA[i] = ((wm + i * 16 + lrow) * SA + lcol) * 2;
    #pragma unroll
    for (int t = 0; t < 2; ++t) offB[t] = ((wn + t * 16 + lrow) * SA + lcol) * 2;

    float acc[4][4][4];
    #pragma unroll
    for (int i = 0; i < 4; ++i)
        #pragma unroll
        for (int j = 0; j < 4; ++j)
            #pragma unroll
            for (int e = 0; e < 4; ++e) acc[i][j][e] = 0.0f;

    // prefetch B chunk 0
    {
        const char* gsrc = (const char*)gb;
        for (int idx = tid; idx < TILE_B / 16; idx += 256)
            cp16(B0_u + idx * 16, gsrc + (size_t)idx * 16);
        asm volatile("cp.async.commit_group;" ::: "memory");
    }

    const int r  = tid >> 1;            // A-gen: row
    const int h8 = (tid & 1) << 3;      // A-gen: feature half

    for (int c = 0; c < nch; ++c) {
        // ---- generate A(c): 16 features -> hi k=d*16+il, lo at +144
        {
            const int f0 = c * 16;
            const float* xrow = X + (size_t)(brow0 + r) * F + f0 + h8;
            float4 v0 = *(const float4*)xrow;
            float4 v1 = *(const float4*)(xrow + 4);
            float xs[8] = {v0.x, v0.y, v0.z, v0.w, v1.x, v1.y, v1.z, v1.w};
            unsigned* Arow = (unsigned*)(As + r * SA);
            #pragma unroll
            for (int p = 0; p < 4; ++p) {
                const int fl = h8 + 2 * p;
                const int f  = f0 + fl;
                float xa = (xs[2*p]   - __ldg(mn + f))     * __ldg(sc + f)     - 1.0f;
                float xb = (xs[2*p+1] - __ldg(mn + f + 1)) * __ldg(sc + f + 1) - 1.0f;
                float Ta[9], Tb[9];
                Ta[0] = 1.0f; Tb[0] = 1.0f; Ta[1] = xa; Tb[1] = xb;
                const float x2a = xa + xa, x2b = xb + xb;
                #pragma unroll
                for (int d = 2; d < 9; ++d) {
                    Ta[d] = fmaf(x2a, Ta[d-1], -Ta[d-2]);
                    Tb[d] = fmaf(x2b, Tb[d-1], -Tb[d-2]);
                }
                #pragma unroll
                for (int d = 0; d < 9; ++d) {
                    __nv_bfloat16 ha = __float2bfloat16(Ta[d]);
                    __nv_bfloat16 hb = __float2bfloat16(Tb[d]);
                    __nv_bfloat16 la = __float2bfloat16(Ta[d] - __bfloat162float(ha));
                    __nv_bfloat16 lb = __float2bfloat16(Tb[d] - __bfloat162float(hb));
                    const int k = d * 16 + fl;
                    Arow[k >> 1] = (unsigned)__bfloat16_as_ushort(ha)
                                 | ((unsigned)__bfloat16_as_ushort(hb) << 16);
                    Arow[(k + 144) >> 1] = (unsigned)__bfloat16_as_ushort(la)
                                         | ((unsigned)__bfloat16_as_ushort(lb) << 16);
                }
            }
        }
        // ---- prefetch next B, wait for current
        if (c + 1 < nch) {
            const char* gsrc = (const char*)(gb + (size_t)(c + 1) * TILE_U32);
            unsigned Bn = B0_u + ((unsigned)(c + 1) & 1u) * TILE_B;
            for (int idx = tid; idx < TILE_B / 16; idx += 256)
                cp16(Bn + idx * 16, gsrc + (size_t)idx * 16);
            asm volatile("cp.async.commit_group;" ::: "memory");
            asm volatile("cp.async.wait_group 1;" ::: "memory");
        } else {
            asm volatile("cp.async.wait_group 0;" ::: "memory");
        }
        __syncthreads();

        // ---- 9 slabs x 3 split terms
        const unsigned Bc = B0_u + ((unsigned)c & 1u) * TILE_B;
        for (int s = 0; s < 9; ++s) {
            const unsigned kh = (unsigned)(s * 32);        // hi slab byte offset
            const unsigned kl = (unsigned)(288 + s * 32);  // lo slab byte offset
            unsigned ah[4][4], al[4][4], bh[2][4], bl[2][4];
            #pragma unroll
            for (int i = 0; i < 4; ++i) {
                ldsm4(A_u + offA[i] + kh, ah[i]);
                ldsm4(A_u + offA[i] + kl, al[i]);
            }
            #pragma unroll
            for (int t = 0; t < 2; ++t) {
                ldsm4(Bc + offB[t] + kh, bh[t]);
                ldsm4(Bc + offB[t] + kl, bl[t]);
            }
            // pass 0: Ah*Bh, pass 1: Ah*Bl, pass 2: Al*Bh (16-apart same-acc reuse)
            #pragma unroll
            for (int pass = 0; pass < 3; ++pass) {
                #pragma unroll
                for (int i = 0; i < 4; ++i)
                    #pragma unroll
                    for (int t = 0; t < 2; ++t)
                        #pragma unroll
                        for (int nb = 0; nb < 2; ++nb) {
                            const unsigned* A = (pass == 2) ? al[i] : ah[i];
                            const unsigned* B = (pass == 1) ? bl[t] : bh[t];
                            mma16816(acc[i][t * 2 + nb], A, B[nb], B[nb + 2]);
                        }
            }
        }
        __syncthreads();
    }

    // ---- epilogue: fragment -> global
    #pragma unroll
    for (int i = 0; i < 4; ++i) {
        const int row0 = brow0 + wm + i * 16 + (lane >> 2);
        #pragma unroll
        for (int j = 0; j < 4; ++j) {
            const int col = oc0 + wn + j * 8 + (lane & 3) * 2;
            float2 vlo = {acc[i][j][0], acc[i][j][1]};
            float2 vhi = {acc[i][j][2], acc[i][j][3]};
            *(float2*)(out + (size_t)row0 * O + col)       = vlo;
            *(float2*)(out + (size_t)(row0 + 8) * O + col) = vhi;
        }
    }
}

// ------------------------------ launcher -----------------------------------
extern "C" void kernel_launch(void* const* d_in, const int* in_sizes, int n_in,
                              void* d_out, int out_size) {
    const float* x  = (const float*)d_in[0];
    const float* c1 = (const float*)d_in[1];
    const float* c2 = (const float*)d_in[2];
    float* y = (float*)d_out;

    float *h, *mn, *sc;
    unsigned *b1, *b2, *mink, *maxk;
    cudaGetSymbolAddress((void**)&h,    g_h);
    cudaGetSymbolAddress((void**)&b1,   g_b1);
    cudaGetSymbolAddress((void**)&b2,   g_b2);
    cudaGetSymbolAddress((void**)&mink, g_mink);
    cudaGetSymbolAddress((void**)&maxk, g_maxk);
    cudaGetSymbolAddress((void**)&mn,   g_mn);
    cudaGetSymbolAddress((void**)&sc,   g_sc);

    cudaFuncSetAttribute(prep_B,  cudaFuncAttributeMaxDynamicSharedMemorySize, 73728);
    cudaFuncSetAttribute(kan_mma, cudaFuncAttributeMaxDynamicSharedMemorySize, 3 * TILE_B);

    const int CHUNK = 256;

    prep_B<<<dim3(HID_DIM / 128, IN_DIM  / 16), 256, 73728>>>(c1, b1, IN_DIM,  HID_DIM);
    prep_B<<<dim3(OUT_DIM / 128, HID_DIM / 16), 256, 73728>>>(c2, b2, HID_DIM, OUT_DIM);

    // ---- layer 1 ----
    minmax_init<<<IN_DIM / 256, 256>>>(mink, maxk, IN_DIM);
    colminmax<<<dim3(IN_DIM / 256, BATCH / CHUNK), 256>>>(x, IN_DIM, CHUNK, mink, maxk);
    finalize_minmax<<<IN_DIM / 256, 256>>>(mink, maxk, mn, sc, IN_DIM);
    kan_mma<<<dim3(HID_DIM / 128, BATCH / 128), 256, 3 * TILE_B>>>(x, b1, mn, sc, h, IN_DIM, HID_DIM);

    // ---- layer 2 ----
    minmax_init<<<HID_DIM / 256, 256>>>(mink, maxk, HID_DIM);
    colminmax<<<dim3(HID_DIM / 256, BATCH / CHUNK), 256>>>(h, HID_DIM, CHUNK, mink, maxk);
    finalize_minmax<<<HID_DIM / 256, 256>>>(mink, maxk, mn, sc, HID_DIM);
    kan_mma<<<dim3(OUT_DIM / 128, BATCH / 128), 256, 3 * TILE_B>>>(h, b2, mn, sc, y, HID_DIM, OUT_DIM);
}

// round 6
// speedup vs baseline: 2.2409x; 1.0006x over previous
#include <cuda_runtime.h>
#include <cuda_bf16.h>
#include <cstdint>

#define BATCH   16384
#define IN_DIM  1024
#define HID_DIM 2048
#define OUT_DIM 1024

#define SA        296                 // padded k-stride (bf16 elems); 592B rows, conflict-free ldmatrix
#define TILE_B    (128 * SA * 2)      // 75776 bytes per operand tile
#define TILE_U32  (TILE_B / 4)        // 18944

// ------------------------------ scratch ------------------------------------
__device__ float    g_h [(size_t)BATCH * HID_DIM];
__device__ unsigned g_b1[(size_t)16 * 64  * TILE_U32];   // layer1 packed B images
__device__ unsigned g_b2[(size_t)8  * 128 * TILE_U32];   // layer2 packed B images
__device__ unsigned g_mink[HID_DIM], g_maxk[HID_DIM];
__device__ float    g_mn[HID_DIM],   g_sc[HID_DIM];

// ---------------------------- helpers --------------------------------------
__device__ __forceinline__ unsigned fkey(float f) {
    unsigned u = __float_as_uint(f);
    return (u & 0x80000000u) ? ~u : (u | 0x80000000u);
}
__device__ __forceinline__ float funkey(unsigned u) {
    return __uint_as_float((u & 0x80000000u) ? (u ^ 0x80000000u) : ~u);
}
__device__ __forceinline__ void cp16(unsigned s, const void* g) {
    asm volatile("cp.async.cg.shared.global [%0], [%1], 16;" :: "r"(s), "l"(g) : "memory");
}
__device__ __forceinline__ void ldsm4(unsigned addr, unsigned* r) {
    asm volatile("ldmatrix.sync.aligned.m8n8.x4.shared.b16 {%0,%1,%2,%3}, [%4];"
                 : "=r"(r[0]), "=r"(r[1]), "=r"(r[2]), "=r"(r[3]) : "r"(addr));
}
__device__ __forceinline__ void mma16816(float* c, const unsigned* a,
                                         unsigned b0, unsigned b1) {
    asm volatile(
        "mma.sync.aligned.m16n8k16.row.col.f32.bf16.bf16.f32 "
        "{%0,%1,%2,%3}, {%4,%5,%6,%7}, {%8,%9}, {%0,%1,%2,%3};"
        : "+f"(c[0]), "+f"(c[1]), "+f"(c[2]), "+f"(c[3])
        : "r"(a[0]), "r"(a[1]), "r"(a[2]), "r"(a[3]), "r"(b0), "r"(b1));
}

// --------------------------- min/max kernels -------------------------------
__global__ void minmax_init(unsigned* mink, unsigned* maxk, int F) {
    int c = blockIdx.x * blockDim.x + threadIdx.x;
    if (c < F) { mink[c] = 0xFFFFFFFFu; maxk[c] = 0u; }
}
__global__ void colminmax(const float* __restrict__ X, int F, int chunk,
                          unsigned* mink, unsigned* maxk) {
    int c  = blockIdx.x * blockDim.x + threadIdx.x;
    int r0 = blockIdx.y * chunk;
    float lo =  3.402823466e38f, hi = -3.402823466e38f;
    const float* p = X + (size_t)r0 * F + c;
    for (int r = 0; r < chunk; ++r) {
        float v = p[(size_t)r * F];
        lo = fminf(lo, v); hi = fmaxf(hi, v);
    }
    atomicMin(&mink[c], fkey(lo));
    atomicMax(&maxk[c], fkey(hi));
}
__global__ void finalize_minmax(const unsigned* mink, const unsigned* maxk,
                                float* mn, float* sc, int F) {
    int c = blockIdx.x * blockDim.x + threadIdx.x;
    if (c < F) {
        float lo = funkey(mink[c]), hi = funkey(maxk[c]);
        mn[c] = lo; sc[c] = 2.0f / (hi - lo);
    }
}

// ------------------------------ B prep -------------------------------------
// coeffs [F,O,9] fp32 -> per (nblock, chunk): exact 75776B smem image.
// row n (0..127), k<144: hi = bf16(c[d*16+il]); 144<=k<288: lo residual;
// k 288..295: zero pad. n-major, stride SA bf16.
__global__ void prep_B(const float* __restrict__ coeffs,
                       unsigned* __restrict__ outB, int F, int O) {
    extern __shared__ float stag[];            // [il][n][d] = 16*128*9 floats
    const int nb = blockIdx.x, c = blockIdx.y, tid = threadIdx.x;
    const float* src = coeffs + ((size_t)(c * 16) * O + (size_t)nb * 128) * 9;
    for (int idx = tid; idx < 18432; idx += 256) {
        int il = idx / 1152, rem = idx - il * 1152;      // rem = n*9 + d
        stag[idx] = src[(size_t)il * O * 9 + rem];
    }
    __syncthreads();
    const int nch = F / 16;
    unsigned* dst = outB + ((size_t)nb * nch + c) * TILE_U32;
    for (int j = tid; j < TILE_U32; j += 256) {
        int nn = j / (SA / 2);
        int k0 = (j - nn * (SA / 2)) * 2;
        unsigned outv = 0;
        if (k0 < 288) {
            #pragma unroll
            for (int e = 0; e < 2; ++e) {
                int k = k0 + e;
                int half = (k >= 144) ? 1 : 0;
                int kk = k - 144 * half;
                int d = kk >> 4, il = kk & 15;
                float v = stag[il * 1152 + nn * 9 + d];
                __nv_bfloat16 hi = __float2bfloat16(v);
                unsigned short us;
                if (half)
                    us = __bfloat16_as_ushort(__float2bfloat16(v - __bfloat162float(hi)));
                else
                    us = __bfloat16_as_ushort(hi);
                outv |= (unsigned)us << (16 * e);
            }
        }
        dst[j] = outv;
    }
}

// ------------------------- fused mma.sync GEMM -----------------------------
// C[128,128] per CTA = sum over chunks of [Ah|Al](gen) x [Bh|Bl](prepped),
// 3-term split: Ah*Bh + Ah*Bl + Al*Bh. 8 warps, warp tile 64x32.
__global__ void __launch_bounds__(256, 1)
kan_mma(const float* __restrict__ X, const unsigned* __restrict__ gB,
        const float* __restrict__ mn, const float* __restrict__ sc,
        float* __restrict__ out, int F, int O)
{
    extern __shared__ __align__(16) char smem[];
    __nv_bfloat16* As = (__nv_bfloat16*)smem;                 // 128 x SA
    const unsigned A_u  = (unsigned)__cvta_generic_to_shared(smem);
    const unsigned B0_u = A_u + TILE_B;                        // double buffer

    const int tid  = threadIdx.x;
    const int wid  = tid >> 5;
    const int lane = tid & 31;
    const int brow0 = blockIdx.y * 128;
    const int oc0   = blockIdx.x * 128;
    const int nch   = F / 16;
    const unsigned* gb = gB + (size_t)blockIdx.x * nch * TILE_U32;

    // ldmatrix per-lane byte offsets (k added per slab)
    const int wm = (wid >> 2) * 64;
    const int wn = (wid & 3) * 32;
    const int lrow = ((lane >> 3) & 1) * 8 + (lane & 7);
    const int lcol = (lane >> 4) * 8;
    unsigned offA[4], offB[2];
    #pragma unroll
    for (int i = 0; i < 4; ++i) offA[i] = ((wm + i * 16 + lrow) * SA + lcol) * 2;
    #pragma unroll
    for (int t = 0; t < 2; ++t) offB[t] = ((wn + t * 16 + lrow) * SA + lcol) * 2;

    float acc[4][4][4];
    #pragma unroll
    for (int i = 0; i < 4; ++i)
        #pragma unroll
        for (int j = 0; j < 4; ++j)
            #pragma unroll
            for (int e = 0; e < 4; ++e) acc[i][j][e] = 0.0f;

    // prefetch B chunk 0
    {
        const char* gsrc = (const char*)gb;
        for (int idx = tid; idx < TILE_B / 16; idx += 256)
            cp16(B0_u + idx * 16, gsrc + (size_t)idx * 16);
        asm volatile("cp.async.commit_group;" ::: "memory");
    }

    const int r  = tid >> 1;            // A-gen: row
    const int h8 = (tid & 1) << 3;      // A-gen: feature half

    for (int c = 0; c < nch; ++c) {
        // ---- generate A(c): 16 features -> hi k=d*16+il, lo at +144
        {
            const int f0 = c * 16;
            const float* xrow = X + (size_t)(brow0 + r) * F + f0 + h8;
            float4 v0 = *(const float4*)xrow;
            float4 v1 = *(const float4*)(xrow + 4);
            float xs[8] = {v0.x, v0.y, v0.z, v0.w, v1.x, v1.y, v1.z, v1.w};
            unsigned* Arow = (unsigned*)(As + r * SA);
            #pragma unroll
            for (int p = 0; p < 4; ++p) {
                const int fl = h8 + 2 * p;
                const int f  = f0 + fl;
                float xa = (xs[2*p]   - __ldg(mn + f))     * __ldg(sc + f)     - 1.0f;
                float xb = (xs[2*p+1] - __ldg(mn + f + 1)) * __ldg(sc + f + 1) - 1.0f;
                float Ta[9], Tb[9];
                Ta[0] = 1.0f; Tb[0] = 1.0f; Ta[1] = xa; Tb[1] = xb;
                const float x2a = xa + xa, x2b = xb + xb;
                #pragma unroll
                for (int d = 2; d < 9; ++d) {
                    Ta[d] = fmaf(x2a, Ta[d-1], -Ta[d-2]);
                    Tb[d] = fmaf(x2b, Tb[d-1], -Tb[d-2]);
                }
                #pragma unroll
                for (int d = 0; d < 9; ++d) {
                    __nv_bfloat16 ha = __float2bfloat16(Ta[d]);
                    __nv_bfloat16 hb = __float2bfloat16(Tb[d]);
                    __nv_bfloat16 la = __float2bfloat16(Ta[d] - __bfloat162float(ha));
                    __nv_bfloat16 lb = __float2bfloat16(Tb[d] - __bfloat162float(hb));
                    const int k = d * 16 + fl;
                    Arow[k >> 1] = (unsigned)__bfloat16_as_ushort(ha)
                                 | ((unsigned)__bfloat16_as_ushort(hb) << 16);
                    Arow[(k + 144) >> 1] = (unsigned)__bfloat16_as_ushort(la)
                                         | ((unsigned)__bfloat16_as_ushort(lb) << 16);
                }
            }
        }
        // ---- prefetch next B, wait for current
        if (c + 1 < nch) {
            const char* gsrc = (const char*)(gb + (size_t)(c + 1) * TILE_U32);
            unsigned Bn = B0_u + ((unsigned)(c + 1) & 1u) * TILE_B;
            for (int idx = tid; idx < TILE_B / 16; idx += 256)
                cp16(Bn + idx * 16, gsrc + (size_t)idx * 16);
            asm volatile("cp.async.commit_group;" ::: "memory");
            asm volatile("cp.async.wait_group 1;" ::: "memory");
        } else {
            asm volatile("cp.async.wait_group 0;" ::: "memory");
        }
        __syncthreads();

        // ---- 9 slabs x 3 split terms
        const unsigned Bc = B0_u + ((unsigned)c & 1u) * TILE_B;
        for (int s = 0; s < 9; ++s) {
            const unsigned kh = (unsigned)(s * 32);        // hi slab byte offset
            const unsigned kl = (unsigned)(288 + s * 32);  // lo slab byte offset
            unsigned ah[4][4], al[4][4], bh[2][4], bl[2][4];
            #pragma unroll
            for (int i = 0; i < 4; ++i) {
                ldsm4(A_u + offA[i] + kh, ah[i]);
                ldsm4(A_u + offA[i] + kl, al[i]);
            }
            #pragma unroll
            for (int t = 0; t < 2; ++t) {
                ldsm4(Bc + offB[t] + kh, bh[t]);
                ldsm4(Bc + offB[t] + kl, bl[t]);
            }
            // pass 0: Ah*Bh, pass 1: Ah*Bl, pass 2: Al*Bh (16-apart same-acc reuse)
            #pragma unroll
            for (int pass = 0; pass < 3; ++pass) {
                #pragma unroll
                for (int i = 0; i < 4; ++i)
                    #pragma unroll
                    for (int t = 0; t < 2; ++t)
                        #pragma unroll
                        for (int nb = 0; nb < 2; ++nb) {
                            const unsigned* A = (pass == 2) ? al[i] : ah[i];
                            const unsigned* B = (pass == 1) ? bl[t] : bh[t];
                            mma16816(acc[i][t * 2 + nb], A, B[nb], B[nb + 2]);
                        }
            }
        }
        __syncthreads();
    }

    // ---- epilogue: fragment -> global
    #pragma unroll
    for (int i = 0; i < 4; ++i) {
        const int row0 = brow0 + wm + i * 16 + (lane >> 2);
        #pragma unroll
        for (int j = 0; j < 4; ++j) {
            const int col = oc0 + wn + j * 8 + (lane & 3) * 2;
            float2 vlo = {acc[i][j][0], acc[i][j][1]};
            float2 vhi = {acc[i][j][2], acc[i][j][3]};
            *(float2*)(out + (size_t)row0 * O + col)       = vlo;
            *(float2*)(out + (size_t)(row0 + 8) * O + col) = vhi;
        }
    }
}

// ------------------------------ launcher -----------------------------------
extern "C" void kernel_launch(void* const* d_in, const int* in_sizes, int n_in,
                              void* d_out, int out_size) {
    const float* x  = (const float*)d_in[0];
    const float* c1 = (const float*)d_in[1];
    const float* c2 = (const float*)d_in[2];
    float* y = (float*)d_out;

    float *h, *mn, *sc;
    unsigned *b1, *b2, *mink, *maxk;
    cudaGetSymbolAddress((void**)&h,    g_h);
    cudaGetSymbolAddress((void**)&b1,   g_b1);
    cudaGetSymbolAddress((void**)&b2,   g_b2);
    cudaGetSymbolAddress((void**)&mink, g_mink);
    cudaGetSymbolAddress((void**)&maxk, g_maxk);
    cudaGetSymbolAddress((void**)&mn,   g_mn);
    cudaGetSymbolAddress((void**)&sc,   g_sc);

    cudaFuncSetAttribute(prep_B,  cudaFuncAttributeMaxDynamicSharedMemorySize, 73728);
    cudaFuncSetAttribute(kan_mma, cudaFuncAttributeMaxDynamicSharedMemorySize, 3 * TILE_B);

    const int CHUNK = 256;

    prep_B<<<dim3(HID_DIM / 128, IN_DIM  / 16), 256, 73728>>>(c1, b1, IN_DIM,  HID_DIM);
    prep_B<<<dim3(OUT_DIM / 128, HID_DIM / 16), 256, 73728>>>(c2, b2, HID_DIM, OUT_DIM);

    // ---- layer 1 ----
    minmax_init<<<IN_DIM / 256, 256>>>(mink, maxk, IN_DIM);
    colminmax<<<dim3(IN_DIM / 256, BATCH / CHUNK), 256>>>(x, IN_DIM, CHUNK, mink, maxk);
    finalize_minmax<<<IN_DIM / 256, 256>>>(mink, maxk, mn, sc, IN_DIM);
    kan_mma<<<dim3(HID_DIM / 128, BATCH / 128), 256, 3 * TILE_B>>>(x, b1, mn, sc, h, IN_DIM, HID_DIM);

    // ---- layer 2 ----
    minmax_init<<<HID_DIM / 256, 256>>>(mink, maxk, HID_DIM);
    colminmax<<<dim3(HID_DIM / 256, BATCH / CHUNK), 256>>>(h, HID_DIM, CHUNK, mink, maxk);
    finalize_minmax<<<HID_DIM / 256, 256>>>(mink, maxk, mn, sc, HID_DIM);
    kan_mma<<<dim3(OUT_DIM / 128, BATCH / 128), 256, 3 * TILE_B>>>(h, b2, mn, sc, y, HID_DIM, OUT_DIM);
}

// round 7
// speedup vs baseline: 6.9964x; 3.1221x over previous
#include <cuda_runtime.h>
#include <cuda_fp16.h>
#include <cstdint>

#define BATCH   16384
#define IN_DIM  1024
#define HID_DIM 2048
#define OUT_DIM 1024

#define SA        136                 // padded k-stride (fp16 elems): 272B rows, conflict-free ldmatrix
#define TILE_B    (128 * SA * 2)      // 34816 bytes per operand tile
#define TILE_U32  (TILE_B / 4)        // 8704

// ------------------------------ scratch ------------------------------------
__device__ float    g_h [(size_t)BATCH * HID_DIM];
__device__ unsigned g_b1[(size_t)16 * 64  * TILE_U32];   // layer1 packed B images
__device__ unsigned g_b2[(size_t)8  * 128 * TILE_U32];   // layer2 packed B images
__device__ float    g_bias1[HID_DIM], g_bias2[OUT_DIM];
__device__ unsigned g_mink[HID_DIM], g_maxk[HID_DIM];
__device__ float    g_mn[HID_DIM],   g_sc[HID_DIM];

// ---------------------------- helpers --------------------------------------
__device__ __forceinline__ unsigned fkey(float f) {
    unsigned u = __float_as_uint(f);
    return (u & 0x80000000u) ? ~u : (u | 0x80000000u);
}
__device__ __forceinline__ float funkey(unsigned u) {
    return __uint_as_float((u & 0x80000000u) ? (u ^ 0x80000000u) : ~u);
}
__device__ __forceinline__ void cp16(unsigned s, const void* g) {
    asm volatile("cp.async.cg.shared.global [%0], [%1], 16;" :: "r"(s), "l"(g) : "memory");
}
__device__ __forceinline__ void ldsm4(unsigned addr, unsigned* r) {
    asm volatile("ldmatrix.sync.aligned.m8n8.x4.shared.b16 {%0,%1,%2,%3}, [%4];"
                 : "=r"(r[0]), "=r"(r[1]), "=r"(r[2]), "=r"(r[3]) : "r"(addr));
}
__device__ __forceinline__ void mma16816(float* c, const unsigned* a,
                                         unsigned b0, unsigned b1) {
    asm volatile(
        "mma.sync.aligned.m16n8k16.row.col.f32.f16.f16.f32 "
        "{%0,%1,%2,%3}, {%4,%5,%6,%7}, {%8,%9}, {%0,%1,%2,%3};"
        : "+f"(c[0]), "+f"(c[1]), "+f"(c[2]), "+f"(c[3])
        : "r"(a[0]), "r"(a[1]), "r"(a[2]), "r"(a[3]), "r"(b0), "r"(b1));
}

// --------------------------- min/max kernels -------------------------------
__global__ void minmax_init(unsigned* mink, unsigned* maxk, int F) {
    int c = blockIdx.x * blockDim.x + threadIdx.x;
    if (c < F) { mink[c] = 0xFFFFFFFFu; maxk[c] = 0u; }
}
__global__ void colminmax(const float* __restrict__ X, int F, int chunk,
                          unsigned* mink, unsigned* maxk) {
    int c  = blockIdx.x * blockDim.x + threadIdx.x;
    int r0 = blockIdx.y * chunk;
    float lo =  3.402823466e38f, hi = -3.402823466e38f;
    const float* p = X + (size_t)r0 * F + c;
    for (int r = 0; r < chunk; ++r) {
        float v = p[(size_t)r * F];
        lo = fminf(lo, v); hi = fmaxf(hi, v);
    }
    atomicMin(&mink[c], fkey(lo));
    atomicMax(&maxk[c], fkey(hi));
}
__global__ void finalize_minmax(const unsigned* mink, const unsigned* maxk,
                                float* mn, float* sc, int F) {
    int c = blockIdx.x * blockDim.x + threadIdx.x;
    if (c < F) {
        float lo = funkey(mink[c]), hi = funkey(maxk[c]);
        mn[c] = lo; sc[c] = 2.0f / (hi - lo);
    }
}

// ------------------------------ bias ---------------------------------------
// bias[o] = sum_i coeffs[i, o, 0]   (T_0 == 1 exactly after normalization)
__global__ void calc_bias(const float* __restrict__ coeffs,
                          float* __restrict__ bias, int F, int O) {
    int o = blockIdx.x * blockDim.x + threadIdx.x;
    if (o >= O) return;
    float s = 0.0f;
    for (int i = 0; i < F; ++i)
        s += coeffs[((size_t)i * O + o) * 9];
    bias[o] = s;
}

// ------------------------------ B prep -------------------------------------
// coeffs [F,O,9] fp32 -> per (nblock, chunk): exact 34816B smem image.
// row n (0..127), col k (0..135): k<128 -> fp16(coeffs[f0 + (k&15), n0+n, (k>>4)+1]),
// k>=128 zero pad. n-major, stride SA fp16.
__global__ void prep_B(const float* __restrict__ coeffs,
                       unsigned* __restrict__ outB, int F, int O) {
    extern __shared__ float stag[];            // [il][n][d] = 16*128*9 floats
    const int nb = blockIdx.x, c = blockIdx.y, tid = threadIdx.x;
    const float* src = coeffs + ((size_t)(c * 16) * O + (size_t)nb * 128) * 9;
    for (int idx = tid; idx < 18432; idx += 256) {
        int il = idx / 1152, rem = idx - il * 1152;      // rem = n*9 + d
        stag[idx] = src[(size_t)il * O * 9 + rem];
    }
    __syncthreads();
    const int nch = F / 16;
    unsigned* dst = outB + ((size_t)nb * nch + c) * TILE_U32;
    for (int j = tid; j < TILE_U32; j += 256) {
        int nn = j / (SA / 2);
        int k0 = (j - nn * (SA / 2)) * 2;
        unsigned outv = 0;
        if (k0 < 128) {
            #pragma unroll
            for (int e = 0; e < 2; ++e) {
                int k  = k0 + e;
                int d  = (k >> 4) + 1;
                int il = k & 15;
                float v = stag[il * 1152 + nn * 9 + d];
                outv |= (unsigned)__half_as_ushort(__float2half_rn(v)) << (16 * e);
            }
        }
        dst[j] = outv;
    }
}

// ------------------------- fused mma.sync GEMM -----------------------------
// C[128,128] per CTA = bias + sum over 16-feature chunks of A(gen) x B(prepped),
// fp16 single-pass, K=128/chunk (degrees 1..8). 8 warps, warp tile 64x32.
__global__ void __launch_bounds__(256, 2)
kan_mma(const float* __restrict__ X, const unsigned* __restrict__ gB,
        const float* __restrict__ mn, const float* __restrict__ sc,
        const float* __restrict__ bias,
        float* __restrict__ out, int F, int O)
{
    extern __shared__ __align__(16) char smem[];
    __half* As = (__half*)smem;                                // 128 x SA
    const unsigned A_u  = (unsigned)__cvta_generic_to_shared(smem);
    const unsigned B0_u = A_u + TILE_B;                        // double buffer

    const int tid  = threadIdx.x;
    const int wid  = tid >> 5;
    const int lane = tid & 31;
    const int brow0 = blockIdx.y * 128;
    const int oc0   = blockIdx.x * 128;
    const int nch   = F / 16;
    const unsigned* gb = gB + (size_t)blockIdx.x * nch * TILE_U32;

    // ldmatrix per-lane byte offsets (slab k-offset added later)
    const int wm = (wid >> 2) * 64;
    const int wn = (wid & 3) * 32;
    const int lrow = ((lane >> 3) & 1) * 8 + (lane & 7);
    const int lcol = (lane >> 4) * 8;
    unsigned offA[4], offB[2];
    #pragma unroll
    for (int i = 0; i < 4; ++i) offA[i] = ((wm + i * 16 + lrow) * SA + lcol) * 2;
    #pragma unroll
    for (int t = 0; t < 2; ++t) offB[t] = ((wn + t * 16 + lrow) * SA + lcol) * 2;

    float acc[4][4][4];
    #pragma unroll
    for (int i = 0; i < 4; ++i)
        #pragma unroll
        for (int j = 0; j < 4; ++j)
            #pragma unroll
            for (int e = 0; e < 4; ++e) acc[i][j][e] = 0.0f;

    // prefetch B chunk 0
    for (int idx = tid; idx < TILE_B / 16; idx += 256)
        cp16(B0_u + idx * 16, (const char*)gb + (size_t)idx * 16);
    asm volatile("cp.async.commit_group;" ::: "memory");

    const int r  = tid >> 1;            // A-gen: row
    const int h8 = (tid & 1) << 3;      // A-gen: feature half

    for (int c = 0; c < nch; ++c) {
        // ---- prefetch next B first (overlaps A-gen)
        if (c + 1 < nch) {
            const char* gsrc = (const char*)(gb + (size_t)(c + 1) * TILE_U32);
            unsigned Bn = B0_u + ((unsigned)(c + 1) & 1u) * TILE_B;
            for (int idx = tid; idx < TILE_B / 16; idx += 256)
                cp16(Bn + idx * 16, gsrc + (size_t)idx * 16);
            asm volatile("cp.async.commit_group;" ::: "memory");
        }

        // ---- generate A(c): 16 features, degrees 1..8 -> k=(d-1)*16+il
        {
            const int f0 = c * 16;
            const float* xrow = X + (size_t)(brow0 + r) * F + f0 + h8;
            float4 v0 = *(const float4*)xrow;
            float4 v1 = *(const float4*)(xrow + 4);
            float xs[8] = {v0.x, v0.y, v0.z, v0.w, v1.x, v1.y, v1.z, v1.w};
            unsigned* Arow = (unsigned*)(As + r * SA);
            #pragma unroll
            for (int p = 0; p < 4; ++p) {
                const int fl = h8 + 2 * p;
                const int f  = f0 + fl;
                float xa = (xs[2*p]   - __ldg(mn + f))     * __ldg(sc + f)     - 1.0f;
                float xb = (xs[2*p+1] - __ldg(mn + f + 1)) * __ldg(sc + f + 1) - 1.0f;
                float Ta = xa, Tb = xb, Pa = 1.0f, Pb = 1.0f;
                const float x2a = xa + xa, x2b = xb + xb;
                #pragma unroll
                for (int d = 1; d < 9; ++d) {
                    Arow[(d - 1) * 8 + (fl >> 1)] =
                          (unsigned)__half_as_ushort(__float2half_rn(Ta))
                        | ((unsigned)__half_as_ushort(__float2half_rn(Tb)) << 16);
                    float na = fmaf(x2a, Ta, -Pa);
                    float nb = fmaf(x2b, Tb, -Pb);
                    Pa = Ta; Pb = Tb; Ta = na; Tb = nb;
                }
            }
        }

        // ---- wait for current B, sync A visible
        if (c + 1 < nch) asm volatile("cp.async.wait_group 1;" ::: "memory");
        else             asm volatile("cp.async.wait_group 0;" ::: "memory");
        __syncthreads();

        // ---- 8 slabs of K=16, single fp16 pass
        const unsigned Bc = B0_u + ((unsigned)c & 1u) * TILE_B;
        #pragma unroll
        for (int s = 0; s < 8; ++s) {
            const unsigned kh = (unsigned)(s * 32);
            unsigned a[4][4], b[2][4];
            #pragma unroll
            for (int i = 0; i < 4; ++i) ldsm4(A_u + offA[i] + kh, a[i]);
            #pragma unroll
            for (int t = 0; t < 2; ++t) ldsm4(Bc + offB[t] + kh, b[t]);
            #pragma unroll
            for (int i = 0; i < 4; ++i)
                #pragma unroll
                for (int t = 0; t < 2; ++t)
                    #pragma unroll
                    for (int nb = 0; nb < 2; ++nb)
                        mma16816(acc[i][t * 2 + nb], a[i], b[t][nb], b[t][nb + 2]);
        }
        __syncthreads();
    }

    // ---- epilogue: add exact d=0 bias, store fp32
    #pragma unroll
    for (int i = 0; i < 4; ++i) {
        const int row0 = brow0 + wm + i * 16 + (lane >> 2);
        #pragma unroll
        for (int j = 0; j < 4; ++j) {
            const int col = oc0 + wn + j * 8 + (lane & 3) * 2;
            const float2 bv = *(const float2*)(bias + col);
            float2 vlo = {acc[i][j][0] + bv.x, acc[i][j][1] + bv.y};
            float2 vhi = {acc[i][j][2] + bv.x, acc[i][j][3] + bv.y};
            *(float2*)(out + (size_t)row0 * O + col)       = vlo;
            *(float2*)(out + (size_t)(row0 + 8) * O + col) = vhi;
        }
    }
}

// ------------------------------ launcher -----------------------------------
extern "C" void kernel_launch(void* const* d_in, const int* in_sizes, int n_in,
                              void* d_out, int out_size) {
    const float* x  = (const float*)d_in[0];
    const float* c1 = (const float*)d_in[1];
    const float* c2 = (const float*)d_in[2];
    float* y = (float*)d_out;

    float *h, *mn, *sc, *bias1, *bias2;
    unsigned *b1, *b2, *mink, *maxk;
    cudaGetSymbolAddress((void**)&h,     g_h);
    cudaGetSymbolAddress((void**)&b1,    g_b1);
    cudaGetSymbolAddress((void**)&b2,    g_b2);
    cudaGetSymbolAddress((void**)&bias1, g_bias1);
    cudaGetSymbolAddress((void**)&bias2, g_bias2);
    cudaGetSymbolAddress((void**)&mink,  g_mink);
    cudaGetSymbolAddress((void**)&maxk,  g_maxk);
    cudaGetSymbolAddress((void**)&mn,    g_mn);
    cudaGetSymbolAddress((void**)&sc,    g_sc);

    cudaFuncSetAttribute(prep_B,  cudaFuncAttributeMaxDynamicSharedMemorySize, 73728);
    cudaFuncSetAttribute(kan_mma, cudaFuncAttributeMaxDynamicSharedMemorySize, 3 * TILE_B);

    const int CHUNK = 256;

    prep_B<<<dim3(HID_DIM / 128, IN_DIM  / 16), 256, 73728>>>(c1, b1, IN_DIM,  HID_DIM);
    prep_B<<<dim3(OUT_DIM / 128, HID_DIM / 16), 256, 73728>>>(c2, b2, HID_DIM, OUT_DIM);
    calc_bias<<<HID_DIM / 256, 256>>>(c1, bias1, IN_DIM,  HID_DIM);
    calc_bias<<<OUT_DIM / 256, 256>>>(c2, bias2, HID_DIM, OUT_DIM);

    // ---- layer 1 ----
    minmax_init<<<IN_DIM / 256, 256>>>(mink, maxk, IN_DIM);
    colminmax<<<dim3(IN_DIM / 256, BATCH / CHUNK), 256>>>(x, IN_DIM, CHUNK, mink, maxk);
    finalize_minmax<<<IN_DIM / 256, 256>>>(mink, maxk, mn, sc, IN_DIM);
    kan_mma<<<dim3(HID_DIM / 128, BATCH / 128), 256, 3 * TILE_B>>>(
        x, b1, mn, sc, bias1, h, IN_DIM, HID_DIM);

    // ---- layer 2 ----
    minmax_init<<<HID_DIM / 256, 256>>>(mink, maxk, HID_DIM);
    colminmax<<<dim3(HID_DIM / 256, BATCH / CHUNK), 256>>>(h, HID_DIM, CHUNK, mink, maxk);
    finalize_minmax<<<HID_DIM / 256, 256>>>(mink, maxk, mn, sc, HID_DIM);
    kan_mma<<<dim3(OUT_DIM / 128, BATCH / 128), 256, 3 * TILE_B>>>(
        h, b2, mn, sc, bias2, y, HID_DIM, OUT_DIM);
}

// round 8
// speedup vs baseline: 7.9162x; 1.1315x over previous
#include <cuda_runtime.h>
#include <cuda_fp16.h>
#include <cstdint>

#define BATCH   16384
#define IN_DIM  1024
#define HID_DIM 2048
#define OUT_DIM 1024

#define SA        72                  // k-stride (fp16): 64 data + 8 pad, 144B rows
#define TILE      18432               // one operand tile: 128 x SA x 2B
#define TILE_U32  4608

// ------------------------------ scratch ------------------------------------
__device__ float    g_h [(size_t)BATCH * HID_DIM];
__device__ unsigned g_b1[(size_t)16 * 128 * TILE_U32];   // layer1 packed B images
__device__ unsigned g_b2[(size_t)8  * 256 * TILE_U32];   // layer2 packed B images
__device__ float    g_bias1[HID_DIM], g_bias2[OUT_DIM];
__device__ float    g_bpart[16][HID_DIM];
__device__ unsigned g_mk1[HID_DIM], g_xk1[HID_DIM];      // layer1 input minmax
__device__ unsigned g_mk2[HID_DIM], g_xk2[HID_DIM];      // layer2 (fused) minmax
__device__ float    g_mn[HID_DIM],  g_sc[HID_DIM];

// ---------------------------- helpers --------------------------------------
__device__ __forceinline__ unsigned fkey(float f) {
    unsigned u = __float_as_uint(f);
    return (u & 0x80000000u) ? ~u : (u | 0x80000000u);
}
__device__ __forceinline__ float funkey(unsigned u) {
    return __uint_as_float((u & 0x80000000u) ? (u ^ 0x80000000u) : ~u);
}
__device__ __forceinline__ void cp16(unsigned s, const void* g) {
    asm volatile("cp.async.cg.shared.global [%0], [%1], 16;" :: "r"(s), "l"(g) : "memory");
}
__device__ __forceinline__ void ldsm4(unsigned addr, unsigned* r) {
    asm volatile("ldmatrix.sync.aligned.m8n8.x4.shared.b16 {%0,%1,%2,%3}, [%4];"
                 : "=r"(r[0]), "=r"(r[1]), "=r"(r[2]), "=r"(r[3]) : "r"(addr));
}
__device__ __forceinline__ void mma16816(float* c, const unsigned* a,
                                         unsigned b0, unsigned b1) {
    asm volatile(
        "mma.sync.aligned.m16n8k16.row.col.f32.f16.f16.f32 "
        "{%0,%1,%2,%3}, {%4,%5,%6,%7}, {%8,%9}, {%0,%1,%2,%3};"
        : "+f"(c[0]), "+f"(c[1]), "+f"(c[2]), "+f"(c[3])
        : "r"(a[0]), "r"(a[1]), "r"(a[2]), "r"(a[3]), "r"(b0), "r"(b1));
}

// --------------------------- min/max kernels -------------------------------
__global__ void minmax_init(unsigned* mink, unsigned* maxk, int F) {
    int c = blockIdx.x * blockDim.x + threadIdx.x;
    if (c < F) { mink[c] = 0xFFFFFFFFu; maxk[c] = 0u; }
}
__global__ void colminmax(const float* __restrict__ X, int F, int chunk,
                          unsigned* mink, unsigned* maxk) {
    int c  = blockIdx.x * blockDim.x + threadIdx.x;
    int r0 = blockIdx.y * chunk;
    float lo =  3.402823466e38f, hi = -3.402823466e38f;
    const float* p = X + (size_t)r0 * F + c;
    for (int r = 0; r < chunk; ++r) {
        float v = p[(size_t)r * F];
        lo = fminf(lo, v); hi = fmaxf(hi, v);
    }
    atomicMin(&mink[c], fkey(lo));
    atomicMax(&maxk[c], fkey(hi));
}
__global__ void finalize_minmax(const unsigned* mink, const unsigned* maxk,
                                float* mn, float* sc, int F) {
    int c = blockIdx.x * blockDim.x + threadIdx.x;
    if (c < F) {
        float lo = funkey(mink[c]), hi = funkey(maxk[c]);
        mn[c] = lo; sc[c] = 2.0f / (hi - lo);
    }
}

// ------------------------------ bias ---------------------------------------
// bias[o] = sum_i coeffs[i, o, 0]  (T_0 == 1 exactly). Deterministic 2-stage.
__global__ void bias_part(const float* __restrict__ coeffs,
                          float* __restrict__ part, int F, int O) {
    int o  = blockIdx.x * blockDim.x + threadIdx.x;
    int i0 = blockIdx.y * 128;
    float s = 0.0f;
    #pragma unroll 4
    for (int i = 0; i < 128; ++i)
        s += coeffs[((size_t)(i0 + i) * O + o) * 9];
    part[blockIdx.y * HID_DIM + o] = s;
}
__global__ void bias_reduce(const float* __restrict__ part,
                            float* __restrict__ bias, int nparts, int O) {
    int o = blockIdx.x * blockDim.x + threadIdx.x;
    float s = 0.0f;
    for (int p = 0; p < nparts; ++p) s += part[p * HID_DIM + o];
    bias[o] = s;
}

// ------------------------------ B prep -------------------------------------
// coeffs [F,O,9] fp32 -> per (nblock, 8-feature chunk): 18432B smem image.
// row n (0..127), col k (0..71): k<64 -> fp16(coeffs[f0+(k&7), n0+n, (k>>3)+1]).
__global__ void prep_B(const float* __restrict__ coeffs,
                       unsigned* __restrict__ outB, int F, int O) {
    __shared__ float stag[8 * 128 * 9];         // [il][n][d]
    const int nb = blockIdx.x, c = blockIdx.y, tid = threadIdx.x;
    const float* src = coeffs + ((size_t)(c * 8) * O + (size_t)nb * 128) * 9;
    for (int idx = tid; idx < 9216; idx += 256) {
        int il = idx / 1152, rem = idx - il * 1152;       // rem = n*9 + d
        stag[idx] = src[(size_t)il * O * 9 + rem];
    }
    __syncthreads();
    const int nch = F / 8;
    unsigned* dst = outB + ((size_t)nb * nch + c) * TILE_U32;
    for (int j = tid; j < TILE_U32; j += 256) {
        int nn = j / 36;
        int k0 = (j - nn * 36) * 2;
        unsigned outv = 0;
        if (k0 < 64) {
            #pragma unroll
            for (int e = 0; e < 2; ++e) {
                int k  = k0 + e;
                int d  = (k >> 3) + 1;
                int il = k & 7;
                float v = stag[il * 1152 + nn * 9 + d];
                outv |= (unsigned)__half_as_ushort(__float2half_rn(v)) << (16 * e);
            }
        }
        dst[j] = outv;
    }
}

// ------------------------- fused mma.sync GEMM -----------------------------
// C[128,128] per CTA = bias + sum over 8-feature chunks (K=64) of A(gen) x B.
// A double-buffered (gen overlapped with MMA), B triple-buffered cp.async.
// Optional fused per-column min/max atomics for the NEXT layer.
__global__ void __launch_bounds__(256, 2)
kan_mma(const float* __restrict__ X, const unsigned* __restrict__ gB,
        const float* __restrict__ mn, const float* __restrict__ sc,
        const float* __restrict__ bias, float* __restrict__ out,
        int F, int O, unsigned* mink2, unsigned* maxk2)
{
    extern __shared__ __align__(16) char smem[];
    const unsigned A_u = (unsigned)__cvta_generic_to_shared(smem);
    const unsigned B_u = A_u + 2 * TILE;                  // 3 stages after 2 A bufs
    __half* As = (__half*)smem;

    const int tid  = threadIdx.x;
    const int wid  = tid >> 5;
    const int lane = tid & 31;
    const int brow0 = blockIdx.y * 128;
    const int oc0   = blockIdx.x * 128;
    const int nch   = F / 8;
    const unsigned* gb = gB + (size_t)blockIdx.x * nch * TILE_U32;

    const int wm = (wid >> 2) * 64;
    const int wn = (wid & 3) * 32;
    const int lrow = ((lane >> 3) & 1) * 8 + (lane & 7);
    const int lcol = (lane >> 4) * 8;
    unsigned offA[4], offB[2];
    #pragma unroll
    for (int i = 0; i < 4; ++i) offA[i] = ((wm + i * 16 + lrow) * SA + lcol) * 2;
    #pragma unroll
    for (int t = 0; t < 2; ++t) offB[t] = ((wn + t * 16 + lrow) * SA + lcol) * 2;

    float acc[4][4][4];
    #pragma unroll
    for (int i = 0; i < 4; ++i)
        #pragma unroll
        for (int j = 0; j < 4; ++j)
            #pragma unroll
            for (int e = 0; e < 4; ++e) acc[i][j][e] = 0.0f;

    const int r  = tid >> 1;            // A-gen: row
    const int h4 = (tid & 1) << 2;      // A-gen: 4-feature half

    // ---- prologue: B(0), B(1) in flight; A(0) generated
    for (int idx = tid; idx < 1152; idx += 256)
        cp16(B_u + idx * 16, (const char*)gb + (size_t)idx * 16);
    asm volatile("cp.async.commit_group;" ::: "memory");
    for (int idx = tid; idx < 1152; idx += 256)
        cp16(B_u + TILE + idx * 16, (const char*)(gb + TILE_U32) + (size_t)idx * 16);
    asm volatile("cp.async.commit_group;" ::: "memory");
    {
        const float4 xv = *(const float4*)(X + (size_t)(brow0 + r) * F + h4);
        const float xs[4] = {xv.x, xv.y, xv.z, xv.w};
        unsigned* Arow = (unsigned*)(As + r * SA);
        #pragma unroll
        for (int p = 0; p < 2; ++p) {
            const int fl = h4 + 2 * p;
            float xa = (xs[2*p]   - __ldg(mn + fl))     * __ldg(sc + fl)     - 1.0f;
            float xb = (xs[2*p+1] - __ldg(mn + fl + 1)) * __ldg(sc + fl + 1) - 1.0f;
            float Ta = xa, Tb = xb, Pa = 1.0f, Pb = 1.0f;
            const float x2a = xa + xa, x2b = xb + xb;
            #pragma unroll
            for (int d = 1; d < 9; ++d) {
                Arow[(d - 1) * 4 + (fl >> 1)] =
                      (unsigned)__half_as_ushort(__float2half_rn(Ta))
                    | ((unsigned)__half_as_ushort(__float2half_rn(Tb)) << 16);
                float na = fmaf(x2a, Ta, -Pa);
                float nb = fmaf(x2b, Tb, -Pb);
                Pa = Ta; Pb = Tb; Ta = na; Tb = nb;
            }
        }
    }
    asm volatile("cp.async.wait_group 1;" ::: "memory");
    __syncthreads();

    int bstage = 0;                     // B stage of chunk c
    for (int c = 0; c < nch; ++c) {
        const unsigned Anow = A_u + ((unsigned)c & 1u) * TILE;
        const unsigned Bc   = B_u + (unsigned)bstage * TILE;

        // 1. issue B(c+2) into stage (bstage+2)%3
        const bool more = (c + 2 < nch);
        if (more) {
            int ns = bstage + 2; if (ns >= 3) ns -= 3;
            const char* gsrc = (const char*)(gb + (size_t)(c + 2) * TILE_U32);
            unsigned Bn = B_u + (unsigned)ns * TILE;
            for (int idx = tid; idx < 1152; idx += 256)
                cp16(Bn + idx * 16, gsrc + (size_t)idx * 16);
            asm volatile("cp.async.commit_group;" ::: "memory");
        }

        // 2. prefetch x for chunk c+1 (LDG latency overlaps MMAs below)
        float4 xv = make_float4(0.f, 0.f, 0.f, 0.f);
        const int f0n = (c + 1) * 8;
        if (c + 1 < nch)
            xv = *(const float4*)(X + (size_t)(brow0 + r) * F + f0n + h4);

        // 3. MMA: 4 slabs of K=16
        #pragma unroll
        for (int s = 0; s < 4; ++s) {
            const unsigned kh = (unsigned)(s * 32);
            unsigned a[4][4], b[2][4];
            #pragma unroll
            for (int i = 0; i < 4; ++i) ldsm4(Anow + offA[i] + kh, a[i]);
            #pragma unroll
            for (int t = 0; t < 2; ++t) ldsm4(Bc + offB[t] + kh, b[t]);
            #pragma unroll
            for (int i = 0; i < 4; ++i)
                #pragma unroll
                for (int t = 0; t < 2; ++t)
                    #pragma unroll
                    for (int nb = 0; nb < 2; ++nb)
                        mma16816(acc[i][t * 2 + nb], a[i], b[t][nb], b[t][nb + 2]);
        }

        // 4. expand A(c+1) into the other A buffer (tensor-shadow work)
        if (c + 1 < nch) {
            const float xs[4] = {xv.x, xv.y, xv.z, xv.w};
            unsigned* Arow = (unsigned*)(As + (((c + 1) & 1) * TILE / 2) + r * SA);
            #pragma unroll
            for (int p = 0; p < 2; ++p) {
                const int fl = h4 + 2 * p;
                const int f  = f0n + fl;
                float xa = (xs[2*p]   - __ldg(mn + f))     * __ldg(sc + f)     - 1.0f;
                float xb = (xs[2*p+1] - __ldg(mn + f + 1)) * __ldg(sc + f + 1) - 1.0f;
                float Ta = xa, Tb = xb, Pa = 1.0f, Pb = 1.0f;
                const float x2a = xa + xa, x2b = xb + xb;
                #pragma unroll
                for (int d = 1; d < 9; ++d) {
                    Arow[(d - 1) * 4 + (fl >> 1)] =
                          (unsigned)__half_as_ushort(__float2half_rn(Ta))
                        | ((unsigned)__half_as_ushort(__float2half_rn(Tb)) << 16);
                    float na = fmaf(x2a, Ta, -Pa);
                    float nb = fmaf(x2b, Tb, -Pb);
                    Pa = Ta; Pb = Tb; Ta = na; Tb = nb;
                }
            }
        }

        // 5. B(c+1) complete; everything visible
        if (more) asm volatile("cp.async.wait_group 1;" ::: "memory");
        else      asm volatile("cp.async.wait_group 0;" ::: "memory");
        __syncthreads();

        if (++bstage >= 3) bstage -= 3;
    }

    // ---- epilogue: + bias, store, fused next-layer column min/max
    #pragma unroll
    for (int j = 0; j < 4; ++j) {
        const int col = oc0 + wn + j * 8 + (lane & 3) * 2;
        const float2 bv = *(const float2*)(bias + col);
        float mnE =  3.402823466e38f, mxE = -3.402823466e38f;
        float mnO =  3.402823466e38f, mxO = -3.402823466e38f;
        #pragma unroll
        for (int i = 0; i < 4; ++i) {
            const int row0 = brow0 + wm + i * 16 + (lane >> 2);
            float2 vlo = {acc[i][j][0] + bv.x, acc[i][j][1] + bv.y};
            float2 vhi = {acc[i][j][2] + bv.x, acc[i][j][3] + bv.y};
            *(float2*)(out + (size_t)row0 * O + col)       = vlo;
            *(float2*)(out + (size_t)(row0 + 8) * O + col) = vhi;
            mnE = fminf(mnE, fminf(vlo.x, vhi.x));
            mxE = fmaxf(mxE, fmaxf(vlo.x, vhi.x));
            mnO = fminf(mnO, fminf(vlo.y, vhi.y));
            mxO = fmaxf(mxO, fmaxf(vlo.y, vhi.y));
        }
        if (mink2 != nullptr) {
            #pragma unroll
            for (int off = 4; off < 32; off <<= 1) {
                mnE = fminf(mnE, __shfl_xor_sync(0xFFFFFFFFu, mnE, off));
                mxE = fmaxf(mxE, __shfl_xor_sync(0xFFFFFFFFu, mxE, off));
                mnO = fminf(mnO, __shfl_xor_sync(0xFFFFFFFFu, mnO, off));
                mxO = fmaxf(mxO, __shfl_xor_sync(0xFFFFFFFFu, mxO, off));
            }
            if (lane < 4) {
                atomicMin(&mink2[col],     fkey(mnE));
                atomicMax(&maxk2[col],     fkey(mxE));
                atomicMin(&mink2[col + 1], fkey(mnO));
                atomicMax(&maxk2[col + 1], fkey(mxO));
            }
        }
    }
}

// ------------------------------ launcher -----------------------------------
extern "C" void kernel_launch(void* const* d_in, const int* in_sizes, int n_in,
                              void* d_out, int out_size) {
    const float* x  = (const float*)d_in[0];
    const float* c1 = (const float*)d_in[1];
    const float* c2 = (const float*)d_in[2];
    float* y = (float*)d_out;

    float *h, *mn, *sc, *bias1, *bias2, *bpart;
    unsigned *b1, *b2, *mk1, *xk1, *mk2, *xk2;
    cudaGetSymbolAddress((void**)&h,     g_h);
    cudaGetSymbolAddress((void**)&b1,    g_b1);
    cudaGetSymbolAddress((void**)&b2,    g_b2);
    cudaGetSymbolAddress((void**)&bias1, g_bias1);
    cudaGetSymbolAddress((void**)&bias2, g_bias2);
    cudaGetSymbolAddress((void**)&bpart, g_bpart);
    cudaGetSymbolAddress((void**)&mk1,   g_mk1);
    cudaGetSymbolAddress((void**)&xk1,   g_xk1);
    cudaGetSymbolAddress((void**)&mk2,   g_mk2);
    cudaGetSymbolAddress((void**)&xk2,   g_xk2);
    cudaGetSymbolAddress((void**)&mn,    g_mn);
    cudaGetSymbolAddress((void**)&sc,    g_sc);

    cudaFuncSetAttribute(kan_mma, cudaFuncAttributeMaxDynamicSharedMemorySize, 5 * TILE);

    // ---- prep: packed B images + biases
    prep_B<<<dim3(16, IN_DIM  / 8), 256>>>(c1, b1, IN_DIM,  HID_DIM);
    prep_B<<<dim3(8,  HID_DIM / 8), 256>>>(c2, b2, HID_DIM, OUT_DIM);
    bias_part<<<dim3(HID_DIM / 256, IN_DIM  / 128), 256>>>(c1, bpart, IN_DIM,  HID_DIM);
    bias_reduce<<<HID_DIM / 256, 256>>>(bpart, bias1, IN_DIM / 128, HID_DIM);
    bias_part<<<dim3(OUT_DIM / 256, HID_DIM / 128), 256>>>(c2, bpart, HID_DIM, OUT_DIM);
    bias_reduce<<<OUT_DIM / 256, 256>>>(bpart, bias2, HID_DIM / 128, OUT_DIM);

    // ---- layer 1 ----
    minmax_init<<<IN_DIM / 256, 256>>>(mk1, xk1, IN_DIM);
    colminmax<<<dim3(IN_DIM / 256, BATCH / 256), 256>>>(x, IN_DIM, 256, mk1, xk1);
    finalize_minmax<<<IN_DIM / 256, 256>>>(mk1, xk1, mn, sc, IN_DIM);
    minmax_init<<<HID_DIM / 256, 256>>>(mk2, xk2, HID_DIM);   // for fused epilogue
    kan_mma<<<dim3(HID_DIM / 128, BATCH / 128), 256, 5 * TILE>>>(
        x, b1, mn, sc, bias1, h, IN_DIM, HID_DIM, mk2, xk2);

    // ---- layer 2 (minmax came from layer-1 epilogue) ----
    finalize_minmax<<<HID_DIM / 256, 256>>>(mk2, xk2, mn, sc, HID_DIM);
    kan_mma<<<dim3(OUT_DIM / 128, BATCH / 128), 256, 5 * TILE>>>(
        h, b2, mn, sc, bias2, y, HID_DIM, OUT_DIM, nullptr, nullptr);
}